// round 1
// baseline (speedup 1.0000x reference)
#include <cuda_runtime.h>

// Problem constants (from reference)
#define BATCH   16384
#define NNEG    10
#define DD      8
#define EE      64
#define NSCORES (BATCH * (1 + NNEG))   // 180224

// One warp per score.
// score id s < BATCH       -> pos_x[s, :]
// score id s >= BATCH      -> neg_x[(s-BATCH), :]  (neg flat index = b*NNEG+n)
//
// pair_sum = sum_{i<j} e_i . e_j = 0.5 * (||sum_r e_r||^2 - sum_r ||e_r||^2)
// per-column decomposition: sum_c 0.5*(S_c^2 - sum_r v_rc^2)
// Lane t owns columns 2t, 2t+1 (float2), so each row load is one coalesced
// 256B transaction per warp; 8 independent loads in flight per lane.

__global__ __launch_bounds__(256) void APE_61555471286335_kernel(
    const int* __restrict__ pos_x,     // [BATCH, DD]
    const int* __restrict__ neg_x,     // [BATCH, NNEG, DD]
    const float* __restrict__ emb,     // [N_ENT, EE]
    const float* __restrict__ pair_w,  // [28]
    const float* __restrict__ c,       // [1]
    float* __restrict__ out)           // [NSCORES] = [pos(B) | neg(B*NNEG)]
{
    const int warp_global = (blockIdx.x * blockDim.x + threadIdx.x) >> 5;
    const int lane = threadIdx.x & 31;
    if (warp_global >= NSCORES) return;

    // Fetch the 8 row indices for this score (lanes 0..7 load, then broadcast).
    const int* idx_ptr = (warp_global < BATCH)
                       ? (pos_x + (size_t)warp_global * DD)
                       : (neg_x + (size_t)(warp_global - BATCH) * DD);
    int my_idx = 0;
    if (lane < DD) my_idx = __ldg(idx_ptr + lane);

    int rows[DD];
#pragma unroll
    for (int r = 0; r < DD; r++)
        rows[r] = __shfl_sync(0xffffffffu, my_idx, r);

    // Issue all 8 gathers back-to-back (MLP=8), then accumulate.
    float2 v[DD];
#pragma unroll
    for (int r = 0; r < DD; r++) {
        const float2* p = reinterpret_cast<const float2*>(
            emb + (size_t)rows[r] * EE) + lane;
        v[r] = __ldg(p);
    }

    float s0 = 0.f, s1 = 0.f, sq = 0.f;
#pragma unroll
    for (int r = 0; r < DD; r++) {
        s0 += v[r].x;
        s1 += v[r].y;
        sq = fmaf(v[r].x, v[r].x, sq);
        sq = fmaf(v[r].y, v[r].y, sq);
    }

    float partial = 0.5f * (s0 * s0 + s1 * s1 - sq);

    // Warp butterfly reduction over the 32 lanes (64 columns).
#pragma unroll
    for (int off = 16; off; off >>= 1)
        partial += __shfl_xor_sync(0xffffffffu, partial, off);

    if (lane == 0) {
        const float scale = expf(__ldg(pair_w));  // exp(pair_w[0]) — faithful to ref
        const float bias  = __ldg(c);
        out[warp_global] = expf(fmaf(partial, scale, bias));
    }
}

extern "C" void kernel_launch(void* const* d_in, const int* in_sizes, int n_in,
                              void* d_out, int out_size) {
    const int*   pos_x  = (const int*)d_in[0];
    const int*   neg_x  = (const int*)d_in[1];
    const float* emb    = (const float*)d_in[2];
    const float* pair_w = (const float*)d_in[3];
    const float* c      = (const float*)d_in[4];
    float*       out    = (float*)d_out;

    const int threads = 256;                       // 8 warps = 8 scores / block
    const int warps_needed = NSCORES;
    const int blocks = (warps_needed * 32 + threads - 1) / threads;  // 22528
    APE_61555471286335_kernel<<<blocks, threads>>>(pos_x, neg_x, emb, pair_w, c, out);
}